// round 5
// baseline (speedup 1.0000x reference)
#include <cuda_runtime.h>
#include <cstdint>

// ---------------------------------------------------------------------------
// VersorLinear (Cl(4,1), 32-dim algebra) == one 4096^3 GEMM + fused L2 norm.
//   Y[b, o*32+k] = sum_{f,i} X[b, f*32+i] * Wc[f*32+i, o*32+k]
//   Wc[(f,i),(o,k)] = W[o,f,i^k] * cayley_sign(i, i^k)
// Round 5: classic mma.sync.m16n8k8.tf32 with ldmatrix fragment loads
// (8 LDSM + 32 HMMA per k-slice instead of 32 LDS + 32 HMMA), 64x64 warp
// tile, raw-fp32 A/B bits (HW tf32 truncation; bias cancels in the fused
// normalization), 3-stage cp.async pipeline, 128 thr/CTA, 2 CTAs/SM.
// ---------------------------------------------------------------------------

#define MDIM 4096
#define NDIM 4096
#define KDIM 4096

// 64 MB folded/transposed weight: g_Wt[n][k]  (n = o*32+k_blade, k = f*32+i)
__device__ float g_Wt[(size_t)NDIM * KDIM];

__device__ __forceinline__ float cayley_sign(int a, int b) {
    int s = 0;
    int aa = a >> 1;
    while (aa) {            // reorder parity
        s += __popc(aa & b);
        aa >>= 1;
    }
    s += ((a & b) >> 4) & 1;  // e4^2 = -1 (SIG=[1,1,1,1,-1])
    return (s & 1) ? -1.0f : 1.0f;
}

// g_Wt[n*4096 + kk] = tf32_rna(W[o,f,i^k] * sign), n=o*32+k, kk=f*32+i
__global__ void fold_kernel(const float* __restrict__ W) {
    int idx = blockIdx.x * blockDim.x + threadIdx.x;
    int kk = idx & (KDIM - 1);
    int n  = idx >> 12;
    int i = kk & 31, f = kk >> 5, k = n & 31, o = n >> 5;
    int j = i ^ k;
    float v = W[(o << 12) + (f << 5) + j] * cayley_sign(i, j);
    uint32_t u;
    asm("cvt.rna.tf32.f32 %0, %1;" : "=r"(u) : "f"(v));
    g_Wt[idx] = __uint_as_float(u);
}

// ---------------------------------------------------------------------------
#define BM 128
#define BN 128
#define BK 32
#define NST 3
#define LDSD 36                         // smem row stride (floats)
#define STG_F (BM * LDSD)               // floats per stage per matrix (4608)

#define CP_ASYNC16(smaddr, gptr) \
    asm volatile("cp.async.cg.shared.global [%0], [%1], 16;" :: "r"(smaddr), "l"(gptr))

#define LDSM_X4(r0, r1, r2, r3, addr)                                          \
    asm volatile("ldmatrix.sync.aligned.m8n8.x4.shared.b16 {%0,%1,%2,%3}, [%4];" \
                 : "=r"(r0), "=r"(r1), "=r"(r2), "=r"(r3) : "r"(addr))

__global__ __launch_bounds__(128, 2)
void gemm_tc_kernel(const float* __restrict__ A, float* __restrict__ C) {
    extern __shared__ float smem[];
    float* As = smem;                    // [NST][BM][LDSD]
    float* Bs = smem + NST * STG_F;      // [NST][BN][LDSD]
    uint32_t sAs = (uint32_t)__cvta_generic_to_shared(As);
    uint32_t sBs = (uint32_t)__cvta_generic_to_shared(Bs);

    const int tid  = threadIdx.x;        // 0..127
    const int lane = tid & 31;
    const int wid  = tid >> 5;           // 0..3
    const int warpM = wid >> 1;          // 0..1 -> 64-row warp tile
    const int warpN = wid & 1;           // 0..1 -> 64-col warp tile
    const int blockRow = blockIdx.y * BM;
    const int blockCol = blockIdx.x * BN;

    // ldmatrix per-lane offset: lanes 0-15 -> rows 0-15 (col 0), 16-31 -> rows
    // 0-15 (col +4 floats). Matches {a0,a1,a2,a3} / {b0,b0',b1,b1'} fragments.
    const uint32_t laneOff = (uint32_t)(((lane & 15) * LDSD + (lane >> 4) * 4) * 4);
    const uint32_t aWarp = sAs + (uint32_t)(warpM * 64 * LDSD * 4) + laneOff;
    const uint32_t bWarp = sBs + (uint32_t)(warpN * 64 * LDSD * 4) + laneOff;

    // gmem->smem: 8 float4 per thread per matrix per stage
    const int r0 = tid >> 3;             // 0..15 (each it adds 16 rows)
    const int c4 = (tid & 7) * 4;        // 0..28
    const float* gA = A    + (size_t)(blockRow + r0) * KDIM + c4;
    const float* gB = g_Wt + (size_t)(blockCol + r0) * KDIM + c4;

#define LOAD_TILE(t, stage) do {                                               \
    const float* _ga = gA + (size_t)(t) * BK;                                  \
    const float* _gb = gB + (size_t)(t) * BK;                                  \
    uint32_t _sa = sAs + (uint32_t)((stage) * STG_F + r0 * LDSD + c4) * 4u;    \
    uint32_t _sb = sBs + (uint32_t)((stage) * STG_F + r0 * LDSD + c4) * 4u;    \
    _Pragma("unroll")                                                          \
    for (int _it = 0; _it < 8; _it++) {                                        \
        CP_ASYNC16(_sa + _it * 16 * LDSD * 4, _ga + (size_t)_it * 16 * KDIM);  \
        CP_ASYNC16(_sb + _it * 16 * LDSD * 4, _gb + (size_t)_it * 16 * KDIM);  \
    }                                                                          \
    asm volatile("cp.async.commit_group;");                                    \
} while (0)

    float acc[4][8][4] = {};             // [mf][nf][c0..c3]

    LOAD_TILE(0, 0);
    LOAD_TILE(1, 1);

    const int T = KDIM / BK;             // 128
    for (int t = 0; t < T; t++) {
        const int stage = t % NST;
        if (t < T - 1) asm volatile("cp.async.wait_group 1;");
        else           asm volatile("cp.async.wait_group 0;");
        __syncthreads();
        if (t + 2 < T) LOAD_TILE(t + 2, (t + 2) % NST);

        const uint32_t aS = aWarp + (uint32_t)(stage * STG_F * 4);
        const uint32_t bS = bWarp + (uint32_t)(stage * STG_F * 4);

#pragma unroll
        for (int ks = 0; ks < 4; ks++) {
            const uint32_t kb = (uint32_t)(ks * 8 * 4);   // k offset in bytes
            uint32_t a[4][4], b[8][2];
#pragma unroll
            for (int mf = 0; mf < 4; mf++)
                LDSM_X4(a[mf][0], a[mf][1], a[mf][2], a[mf][3],
                        aS + (uint32_t)(mf * 16 * LDSD * 4) + kb);
#pragma unroll
            for (int p = 0; p < 4; p++)   // two n-groups per ldmatrix
                LDSM_X4(b[2*p][0], b[2*p+1][0], b[2*p][1], b[2*p+1][1],
                        bS + (uint32_t)(p * 16 * LDSD * 4) + kb);
#pragma unroll
            for (int mf = 0; mf < 4; mf++)
#pragma unroll
                for (int nf = 0; nf < 8; nf++)
                    asm volatile(
                        "mma.sync.aligned.m16n8k8.row.col.f32.tf32.tf32.f32 "
                        "{%0,%1,%2,%3}, {%4,%5,%6,%7}, {%8,%9}, {%0,%1,%2,%3};"
                        : "+f"(acc[mf][nf][0]), "+f"(acc[mf][nf][1]),
                          "+f"(acc[mf][nf][2]), "+f"(acc[mf][nf][3])
                        : "r"(a[mf][0]), "r"(a[mf][1]), "r"(a[mf][2]), "r"(a[mf][3]),
                          "r"(b[nf][0]), "r"(b[nf][1]));
        }
        __syncthreads();
    }

    // ---- fused manifold normalization + store ----
    // Warp tile cols [warpN*64, warpN*64+64) = two 32-col blade groups:
    // nf 0..3 -> group A, nf 4..7 -> group B. Row r's group values live in
    // the lane quad sharing (lane>>2): shfl_xor(1|2) reduces within it.
#pragma unroll
    for (int mf = 0; mf < 4; mf++) {
        float sA0 = 0.f, sA1 = 0.f, sB0 = 0.f, sB1 = 0.f;
#pragma unroll
        for (int nf = 0; nf < 4; nf++) {
            sA0 += acc[mf][nf][0] * acc[mf][nf][0] + acc[mf][nf][1] * acc[mf][nf][1];
            sA1 += acc[mf][nf][2] * acc[mf][nf][2] + acc[mf][nf][3] * acc[mf][nf][3];
            sB0 += acc[mf][nf+4][0] * acc[mf][nf+4][0] + acc[mf][nf+4][1] * acc[mf][nf+4][1];
            sB1 += acc[mf][nf+4][2] * acc[mf][nf+4][2] + acc[mf][nf+4][3] * acc[mf][nf+4][3];
        }
        sA0 += __shfl_xor_sync(0xffffffffu, sA0, 1);
        sA0 += __shfl_xor_sync(0xffffffffu, sA0, 2);
        sA1 += __shfl_xor_sync(0xffffffffu, sA1, 1);
        sA1 += __shfl_xor_sync(0xffffffffu, sA1, 2);
        sB0 += __shfl_xor_sync(0xffffffffu, sB0, 1);
        sB0 += __shfl_xor_sync(0xffffffffu, sB0, 2);
        sB1 += __shfl_xor_sync(0xffffffffu, sB1, 1);
        sB1 += __shfl_xor_sync(0xffffffffu, sB1, 2);
        float iA0 = rsqrtf(sA0 + 1e-6f), iA1 = rsqrtf(sA1 + 1e-6f);
        float iB0 = rsqrtf(sB0 + 1e-6f), iB1 = rsqrtf(sB1 + 1e-6f);

        int rlo  = blockRow + warpM * 64 + mf * 16 + (lane >> 2);
        int col0 = blockCol + warpN * 64 + (lane & 3) * 2;
#pragma unroll
        for (int nf = 0; nf < 8; nf++) {
            float i0 = (nf < 4) ? iA0 : iB0;
            float i1 = (nf < 4) ? iA1 : iB1;
            *reinterpret_cast<float2*>(C + (size_t)rlo * NDIM + col0 + nf * 8) =
                make_float2(acc[mf][nf][0] * i0, acc[mf][nf][1] * i0);
            *reinterpret_cast<float2*>(C + (size_t)(rlo + 8) * NDIM + col0 + nf * 8) =
                make_float2(acc[mf][nf][2] * i1, acc[mf][nf][3] * i1);
        }
    }
}

// ---------------------------------------------------------------------------
extern "C" void kernel_launch(void* const* d_in, const int* in_sizes, int n_in,
                              void* d_out, int out_size) {
    const float* x = (const float*)d_in[0];
    const float* w = (const float*)d_in[1];
    if (n_in >= 2 && in_sizes[0] == 524288 && in_sizes[1] == 16777216) {
        const float* t = x; x = w; w = t;  // defensive order swap
    }
    float* y = (float*)d_out;

    fold_kernel<<<65536, 256>>>(w);  // 16,777,216 elements

    const int smem_bytes = NST * 2 * STG_F * (int)sizeof(float);  // 110592
    cudaFuncSetAttribute(gemm_tc_kernel,
                         cudaFuncAttributeMaxDynamicSharedMemorySize, smem_bytes);
    dim3 grid(NDIM / BN, MDIM / BM);  // 32 x 32
    gemm_tc_kernel<<<grid, 128, smem_bytes>>>(x, y);
}

// round 6
// speedup vs baseline: 1.0469x; 1.0469x over previous
#include <cuda_runtime.h>
#include <cstdint>

// ---------------------------------------------------------------------------
// VersorLinear (Cl(4,1), 32-dim algebra) == one 4096^3 GEMM + fused L2 norm.
//   Y[b, o*32+k] = sum_{f,i} X[b, f*32+i] * Wc[f*32+i, o*32+k]
//   Wc[(f,i),(o,k)] = W[o,f,i^k] * cayley_sign(i, i^k)
// Round 6: classic mma.sync.m16n8k8.tf32, latency-hiding config:
//   - 256 thr/CTA, 8 warps, 64x32 warp tile -> 4 warps/SMSP (2 CTAs/SM)
//   - raw fp32 bits into the MMA (HW tf32 truncation; bias cancels in the
//     fused normalization) -- no CVT, no ldmatrix (round-5 ALU regression)
//   - 3-stage cp.async ring, ONE __syncthreads per k-tile
// ---------------------------------------------------------------------------

#define MDIM 4096
#define NDIM 4096
#define KDIM 4096

// 64 MB folded/transposed weight: g_Wt[n][k]  (n = o*32+k_blade, k = f*32+i)
__device__ float g_Wt[(size_t)NDIM * KDIM];

__device__ __forceinline__ float cayley_sign(int a, int b) {
    int s = 0;
    int aa = a >> 1;
    while (aa) {            // reorder parity
        s += __popc(aa & b);
        aa >>= 1;
    }
    s += ((a & b) >> 4) & 1;  // e4^2 = -1 (SIG=[1,1,1,1,-1])
    return (s & 1) ? -1.0f : 1.0f;
}

// g_Wt[n*4096 + kk] = tf32_rna(W[o,f,i^k] * sign); vectorized float4 stores.
__global__ void fold_kernel(const float* __restrict__ W) {
    int idx4 = blockIdx.x * blockDim.x + threadIdx.x;  // 0 .. 4194303
    int base = idx4 << 2;
    int n  = base >> 12;            // o*32 + k (same for all 4)
    int kk = base & (KDIM - 1);     // f*32 + i0
    int k = n & 31, o = n >> 5, f = kk >> 5, i0 = kk & 31;
    const float* wrow = W + (o << 12) + (f << 5);
    float4 out;
    float* po = &out.x;
#pragma unroll
    for (int d = 0; d < 4; d++) {
        int i = i0 + d;
        int j = i ^ k;
        float v = wrow[j] * cayley_sign(i, j);
        uint32_t u;
        asm("cvt.rna.tf32.f32 %0, %1;" : "=r"(u) : "f"(v));
        po[d] = __uint_as_float(u);
    }
    *reinterpret_cast<float4*>(&g_Wt[base]) = out;
}

// ---------------------------------------------------------------------------
#define BM 128
#define BN 128
#define BK 32
#define NST 3
#define LDSD 36                         // smem row stride (floats)
#define STG_F (BM * LDSD)               // floats per stage per matrix (4608)

#define CP_ASYNC16(smaddr, gptr) \
    asm volatile("cp.async.cg.shared.global [%0], [%1], 16;" :: "r"(smaddr), "l"(gptr))

__global__ __launch_bounds__(256, 2)
void gemm_tc_kernel(const float* __restrict__ A, float* __restrict__ C) {
    extern __shared__ float smem[];
    float* As = smem;                    // [NST][BM][LDSD]
    float* Bs = smem + NST * STG_F;      // [NST][BN][LDSD]
    uint32_t sAs = (uint32_t)__cvta_generic_to_shared(As);
    uint32_t sBs = (uint32_t)__cvta_generic_to_shared(Bs);

    const int tid  = threadIdx.x;        // 0..255
    const int lane = tid & 31;
    const int wid  = tid >> 5;           // 0..7
    const int warpM = wid >> 2;          // 0..1 -> 64-row warp tile
    const int warpN = wid & 3;           // 0..3 -> 32-col warp tile
    const int blockRow = blockIdx.y * BM;
    const int blockCol = blockIdx.x * BN;

    // gmem->smem: 4 float4 per thread per matrix per stage
    const int r0 = tid >> 3;             // 0..31 (each it adds 32 rows)
    const int c4 = (tid & 7) * 4;        // 0..28
    const float* gA = A    + (size_t)(blockRow + r0) * KDIM + c4;
    const float* gB = g_Wt + (size_t)(blockCol + r0) * KDIM + c4;

#define LOAD_TILE(t, stage) do {                                               \
    const float* _ga = gA + (size_t)(t) * BK;                                  \
    const float* _gb = gB + (size_t)(t) * BK;                                  \
    uint32_t _sa = sAs + (uint32_t)((stage) * STG_F + r0 * LDSD + c4) * 4u;    \
    uint32_t _sb = sBs + (uint32_t)((stage) * STG_F + r0 * LDSD + c4) * 4u;    \
    _Pragma("unroll")                                                          \
    for (int _it = 0; _it < 4; _it++) {                                        \
        CP_ASYNC16(_sa + _it * 32 * LDSD * 4, _ga + (size_t)_it * 32 * KDIM);  \
        CP_ASYNC16(_sb + _it * 32 * LDSD * 4, _gb + (size_t)_it * 32 * KDIM);  \
    }                                                                          \
    asm volatile("cp.async.commit_group;");                                    \
} while (0)

    float acc[4][4][4] = {};             // [mf][nf][c0..c3]

    LOAD_TILE(0, 0);
    LOAD_TILE(1, 1);

    const int T = KDIM / BK;             // 128
    for (int t = 0; t < T; t++) {
        const int stage = t % NST;
        if (t < T - 1) asm volatile("cp.async.wait_group 1;");
        else           asm volatile("cp.async.wait_group 0;");
        __syncthreads();                 // single barrier per tile: orders both
                                         // stage-read readiness and stage reuse
        if (t + 2 < T) LOAD_TILE(t + 2, (t + 2) % NST);

        const float* as = As + stage * STG_F
                        + (warpM * 64 + (lane >> 2)) * LDSD + (lane & 3);
        const float* bs = Bs + stage * STG_F
                        + (warpN * 32 + (lane >> 2)) * LDSD + (lane & 3);

#pragma unroll
        for (int ks = 0; ks < 4; ks++) {
            const int kof = ks * 8;
            uint32_t a[4][4], b[4][2];
#pragma unroll
            for (int mf = 0; mf < 4; mf++) {
                // raw fp32 bits: HW truncates to tf32 inside the MMA
                a[mf][0] = __float_as_uint(as[(mf * 16    ) * LDSD + kof    ]);
                a[mf][1] = __float_as_uint(as[(mf * 16 + 8) * LDSD + kof    ]);
                a[mf][2] = __float_as_uint(as[(mf * 16    ) * LDSD + kof + 4]);
                a[mf][3] = __float_as_uint(as[(mf * 16 + 8) * LDSD + kof + 4]);
            }
#pragma unroll
            for (int nf = 0; nf < 4; nf++) {
                b[nf][0] = __float_as_uint(bs[(nf * 8) * LDSD + kof    ]);
                b[nf][1] = __float_as_uint(bs[(nf * 8) * LDSD + kof + 4]);
            }
#pragma unroll
            for (int mf = 0; mf < 4; mf++)
#pragma unroll
                for (int nf = 0; nf < 4; nf++)
                    asm volatile(
                        "mma.sync.aligned.m16n8k8.row.col.f32.tf32.tf32.f32 "
                        "{%0,%1,%2,%3}, {%4,%5,%6,%7}, {%8,%9}, {%0,%1,%2,%3};"
                        : "+f"(acc[mf][nf][0]), "+f"(acc[mf][nf][1]),
                          "+f"(acc[mf][nf][2]), "+f"(acc[mf][nf][3])
                        : "r"(a[mf][0]), "r"(a[mf][1]), "r"(a[mf][2]), "r"(a[mf][3]),
                          "r"(b[nf][0]), "r"(b[nf][1]));
        }
        // no trailing barrier: next iteration's top barrier provides the
        // ordering before stage (t+2)%NST is overwritten (it was read at t-1)
    }

    // ---- fused manifold normalization + store ----
    // Warp tile cols [warpN*32, warpN*32+32) = exactly one blade group.
    // Row r's 32 values live in the lane quad sharing (lane>>2).
#pragma unroll
    for (int mf = 0; mf < 4; mf++) {
        float slo = 0.f, shi = 0.f;
#pragma unroll
        for (int nf = 0; nf < 4; nf++) {
            slo += acc[mf][nf][0] * acc[mf][nf][0] + acc[mf][nf][1] * acc[mf][nf][1];
            shi += acc[mf][nf][2] * acc[mf][nf][2] + acc[mf][nf][3] * acc[mf][nf][3];
        }
        slo += __shfl_xor_sync(0xffffffffu, slo, 1);
        slo += __shfl_xor_sync(0xffffffffu, slo, 2);
        shi += __shfl_xor_sync(0xffffffffu, shi, 1);
        shi += __shfl_xor_sync(0xffffffffu, shi, 2);
        float ilo = rsqrtf(slo + 1e-6f);
        float ihi = rsqrtf(shi + 1e-6f);

        int rlo  = blockRow + warpM * 64 + mf * 16 + (lane >> 2);
        int col0 = blockCol + warpN * 32 + (lane & 3) * 2;
#pragma unroll
        for (int nf = 0; nf < 4; nf++) {
            *reinterpret_cast<float2*>(C + (size_t)rlo * NDIM + col0 + nf * 8) =
                make_float2(acc[mf][nf][0] * ilo, acc[mf][nf][1] * ilo);
            *reinterpret_cast<float2*>(C + (size_t)(rlo + 8) * NDIM + col0 + nf * 8) =
                make_float2(acc[mf][nf][2] * ihi, acc[mf][nf][3] * ihi);
        }
    }
}

// ---------------------------------------------------------------------------
extern "C" void kernel_launch(void* const* d_in, const int* in_sizes, int n_in,
                              void* d_out, int out_size) {
    const float* x = (const float*)d_in[0];
    const float* w = (const float*)d_in[1];
    if (n_in >= 2 && in_sizes[0] == 524288 && in_sizes[1] == 16777216) {
        const float* t = x; x = w; w = t;  // defensive order swap
    }
    float* y = (float*)d_out;

    fold_kernel<<<16384, 256>>>(w);  // 4,194,304 float4 stores

    const int smem_bytes = NST * 2 * STG_F * (int)sizeof(float);  // 110592
    cudaFuncSetAttribute(gemm_tc_kernel,
                         cudaFuncAttributeMaxDynamicSharedMemorySize, smem_bytes);
    dim3 grid(NDIM / BN, MDIM / BM);  // 32 x 32
    gemm_tc_kernel<<<grid, 256, smem_bytes>>>(x, y);
}

// round 7
// speedup vs baseline: 1.6672x; 1.5925x over previous
#include <cuda_runtime.h>
#include <cuda_fp16.h>
#include <cstdint>

// ---------------------------------------------------------------------------
// VersorLinear (Cl(4,1), 32-dim algebra) == one 4096^3 GEMM + fused L2 norm.
//   Y[b, o*32+k] = sum_{f,i} X[b, f*32+i] * Wc[f*32+i, o*32+k]
//   Wc[(f,i),(o,k)] = W[o,f,i^k] * cayley_sign(i, i^k)
// Round 7: fp16 mma.sync.m16n8k16 with fp32 accumulation.
//   Rationale: legacy tf32 HMMA saturates the sm_103a tensor pipe at ~56%
//   "active" regardless of config (4 configs, invariant) -> per-instruction
//   ceiling. fp16 k16 doubles MACs/instruction at the same issue rate and
//   the SAME 10-bit mantissa as tf32 (rel_err stays ~3-5e-4).
//   - x pre-converted to fp16 (g_Xh), weight folded directly to fp16 (g_Wh)
//   - 256 thr/CTA, 8 warps, 64x32 warp tile, 2 CTAs/SM
//   - 4-stage cp.async ring (80 KB smem), one __syncthreads per k-tile
// ---------------------------------------------------------------------------

#define MDIM 4096
#define NDIM 4096
#define KDIM 4096

__device__ __half g_Wh[(size_t)NDIM * KDIM];   // folded weight, [n][k], fp16
__device__ __half g_Xh[(size_t)MDIM * KDIM];   // x in fp16, [m][k]

__device__ __forceinline__ float cayley_sign(int a, int b) {
    int s = 0;
    int aa = a >> 1;
    while (aa) {            // reorder parity
        s += __popc(aa & b);
        aa >>= 1;
    }
    s += ((a & b) >> 4) & 1;  // e4^2 = -1 (SIG=[1,1,1,1,-1])
    return (s & 1) ? -1.0f : 1.0f;
}

// g_Wh[n*4096 + kk] = fp16(W[o,f,i^k] * sign), n=o*32+k, kk=f*32+i
// 8 elements per thread (one 16B store).
__global__ void fold_kernel(const float* __restrict__ W) {
    int idx8 = blockIdx.x * blockDim.x + threadIdx.x;   // 0 .. 2097151
    int base = idx8 << 3;
    int n  = base >> 12;            // o*32 + k
    int kk = base & (KDIM - 1);     // f*32 + i0 (i0 multiple of 8)
    int k = n & 31, o = n >> 5, f = kk >> 5, i0 = kk & 31;
    const float* wrow = W + (o << 12) + (f << 5);
    __half h[8];
#pragma unroll
    for (int d = 0; d < 8; d++) {
        int i = i0 + d;
        int j = i ^ k;
        h[d] = __float2half_rn(wrow[j] * cayley_sign(i, j));
    }
    *reinterpret_cast<uint4*>(&g_Wh[base]) = *reinterpret_cast<uint4*>(h);
}

// x (fp32) -> g_Xh (fp16), 8 elements per thread
__global__ void cvt_x_kernel(const float* __restrict__ X) {
    int idx8 = blockIdx.x * blockDim.x + threadIdx.x;   // 0 .. 2097151
    size_t base = (size_t)idx8 << 3;
    float4 v0 = *reinterpret_cast<const float4*>(X + base);
    float4 v1 = *reinterpret_cast<const float4*>(X + base + 4);
    __half h[8];
    h[0] = __float2half_rn(v0.x); h[1] = __float2half_rn(v0.y);
    h[2] = __float2half_rn(v0.z); h[3] = __float2half_rn(v0.w);
    h[4] = __float2half_rn(v1.x); h[5] = __float2half_rn(v1.y);
    h[6] = __float2half_rn(v1.z); h[7] = __float2half_rn(v1.w);
    *reinterpret_cast<uint4*>(&g_Xh[base]) = *reinterpret_cast<uint4*>(h);
}

// ---------------------------------------------------------------------------
#define BM 128
#define BN 128
#define BK 32
#define NST 4
#define LDSD 40                          // smem row stride in HALFS (80 B)
#define STG_H (BM * LDSD)                // halfs per stage per matrix (5120)

#define CP_ASYNC16(smaddr, gptr) \
    asm volatile("cp.async.cg.shared.global [%0], [%1], 16;" :: "r"(smaddr), "l"(gptr))

__global__ __launch_bounds__(256, 2)
void gemm_tc_kernel(float* __restrict__ C) {
    extern __shared__ __half smem[];
    __half* As = smem;                    // [NST][BM][LDSD]
    __half* Bs = smem + NST * STG_H;      // [NST][BN][LDSD]
    uint32_t sAs = (uint32_t)__cvta_generic_to_shared(As);
    uint32_t sBs = (uint32_t)__cvta_generic_to_shared(Bs);

    const int tid  = threadIdx.x;        // 0..255
    const int lane = tid & 31;
    const int wid  = tid >> 5;           // 0..7
    const int warpM = wid >> 2;          // 0..1 -> 64-row warp tile
    const int warpN = wid & 3;           // 0..3 -> 32-col warp tile
    const int blockRow = blockIdx.y * BM;
    const int blockCol = blockIdx.x * BN;

    // gmem->smem: each row is 32 halfs = 64 B = 4 x 16B chunks.
    // 512 chunks per matrix per stage / 256 threads = 2 per thread.
    const int r0 = tid >> 2;             // 0..63 (it adds 64 rows)
    const int c8 = (tid & 3) * 8;        // half offset within row: 0,8,16,24
    const __half* gA = g_Xh + (size_t)(blockRow + r0) * KDIM + c8;
    const __half* gB = g_Wh + (size_t)(blockCol + r0) * KDIM + c8;

#define LOAD_TILE(t, stage) do {                                               \
    const __half* _ga = gA + (size_t)(t) * BK;                                 \
    const __half* _gb = gB + (size_t)(t) * BK;                                 \
    uint32_t _sa = sAs + (uint32_t)((stage) * STG_H + r0 * LDSD + c8) * 2u;    \
    uint32_t _sb = sBs + (uint32_t)((stage) * STG_H + r0 * LDSD + c8) * 2u;    \
    CP_ASYNC16(_sa,                      _ga);                                 \
    CP_ASYNC16(_sa + 64 * LDSD * 2,      _ga + (size_t)64 * KDIM);             \
    CP_ASYNC16(_sb,                      _gb);                                 \
    CP_ASYNC16(_sb + 64 * LDSD * 2,      _gb + (size_t)64 * KDIM);             \
    asm volatile("cp.async.commit_group;");                                    \
} while (0)

    float acc[4][4][4] = {};             // [mf][nf][c0..c3]

    LOAD_TILE(0, 0);
    LOAD_TILE(1, 1);
    LOAD_TILE(2, 2);

    // fragment base offsets (halfs)
    const int aRowBase = warpM * 64 + (lane >> 2);   // + mf*16 (+8)
    const int t2 = (lane & 3) * 2;                   // k pair within 8
    const int bRowBase = warpN * 32 + (lane >> 2);   // + nf*8

    const int T = KDIM / BK;             // 128
    for (int t = 0; t < T; t++) {
        const int stage = t & (NST - 1);
        if (t < T - 1) asm volatile("cp.async.wait_group 2;");
        else           asm volatile("cp.async.wait_group 0;");
        __syncthreads();
        if (t + 3 < T) LOAD_TILE(t + 3, (t + 3) & (NST - 1));

        const __half* as = As + stage * STG_H + aRowBase * LDSD + t2;
        const __half* bs = Bs + stage * STG_H + bRowBase * LDSD + t2;

#pragma unroll
        for (int ks = 0; ks < 2; ks++) {             // two k16 slices in BK=32
            const int kof = ks * 16;
            uint32_t a[4][4], b[4][2];
#pragma unroll
            for (int mf = 0; mf < 4; mf++) {
                a[mf][0] = *reinterpret_cast<const uint32_t*>(&as[(mf * 16    ) * LDSD + kof    ]);
                a[mf][1] = *reinterpret_cast<const uint32_t*>(&as[(mf * 16 + 8) * LDSD + kof    ]);
                a[mf][2] = *reinterpret_cast<const uint32_t*>(&as[(mf * 16    ) * LDSD + kof + 8]);
                a[mf][3] = *reinterpret_cast<const uint32_t*>(&as[(mf * 16 + 8) * LDSD + kof + 8]);
            }
#pragma unroll
            for (int nf = 0; nf < 4; nf++) {
                b[nf][0] = *reinterpret_cast<const uint32_t*>(&bs[(nf * 8) * LDSD + kof    ]);
                b[nf][1] = *reinterpret_cast<const uint32_t*>(&bs[(nf * 8) * LDSD + kof + 8]);
            }
#pragma unroll
            for (int mf = 0; mf < 4; mf++)
#pragma unroll
                for (int nf = 0; nf < 4; nf++)
                    asm volatile(
                        "mma.sync.aligned.m16n8k16.row.col.f32.f16.f16.f32 "
                        "{%0,%1,%2,%3}, {%4,%5,%6,%7}, {%8,%9}, {%0,%1,%2,%3};"
                        : "+f"(acc[mf][nf][0]), "+f"(acc[mf][nf][1]),
                          "+f"(acc[mf][nf][2]), "+f"(acc[mf][nf][3])
                        : "r"(a[mf][0]), "r"(a[mf][1]), "r"(a[mf][2]), "r"(a[mf][3]),
                          "r"(b[nf][0]), "r"(b[nf][1]));
        }
        // stage (t+3)%NST written after barrier(t) was last read at t-1: safe
    }

    // ---- fused manifold normalization + store ----
    // Warp tile cols [warpN*32, warpN*32+32) = exactly one blade group.
    // Row r's 32 values live in the lane quad sharing (lane>>2).
#pragma unroll
    for (int mf = 0; mf < 4; mf++) {
        float slo = 0.f, shi = 0.f;
#pragma unroll
        for (int nf = 0; nf < 4; nf++) {
            slo += acc[mf][nf][0] * acc[mf][nf][0] + acc[mf][nf][1] * acc[mf][nf][1];
            shi += acc[mf][nf][2] * acc[mf][nf][2] + acc[mf][nf][3] * acc[mf][nf][3];
        }
        slo += __shfl_xor_sync(0xffffffffu, slo, 1);
        slo += __shfl_xor_sync(0xffffffffu, slo, 2);
        shi += __shfl_xor_sync(0xffffffffu, shi, 1);
        shi += __shfl_xor_sync(0xffffffffu, shi, 2);
        float ilo = rsqrtf(slo + 1e-6f);
        float ihi = rsqrtf(shi + 1e-6f);

        int rlo  = blockRow + warpM * 64 + mf * 16 + (lane >> 2);
        int col0 = blockCol + warpN * 32 + (lane & 3) * 2;
#pragma unroll
        for (int nf = 0; nf < 4; nf++) {
            *reinterpret_cast<float2*>(C + (size_t)rlo * NDIM + col0 + nf * 8) =
                make_float2(acc[mf][nf][0] * ilo, acc[mf][nf][1] * ilo);
            *reinterpret_cast<float2*>(C + (size_t)(rlo + 8) * NDIM + col0 + nf * 8) =
                make_float2(acc[mf][nf][2] * ihi, acc[mf][nf][3] * ihi);
        }
    }
}

// ---------------------------------------------------------------------------
extern "C" void kernel_launch(void* const* d_in, const int* in_sizes, int n_in,
                              void* d_out, int out_size) {
    const float* x = (const float*)d_in[0];
    const float* w = (const float*)d_in[1];
    if (n_in >= 2 && in_sizes[0] == 524288 && in_sizes[1] == 16777216) {
        const float* t = x; x = w; w = t;  // defensive order swap
    }
    float* y = (float*)d_out;

    fold_kernel<<<8192, 256>>>(w);    // 2,097,152 x 8-elem fp16 stores
    cvt_x_kernel<<<8192, 256>>>(x);   // x -> fp16

    const int smem_bytes = NST * 2 * STG_H * (int)sizeof(__half);  // 81920
    cudaFuncSetAttribute(gemm_tc_kernel,
                         cudaFuncAttributeMaxDynamicSharedMemorySize, smem_bytes);
    dim3 grid(NDIM / BN, MDIM / BM);  // 32 x 32
    gemm_tc_kernel<<<grid, 256, smem_bytes>>>(y);
}